// round 8
// baseline (speedup 1.0000x reference)
#include <cuda_runtime.h>
#include <cstdint>

// Problem constants
#define N_BATCH 2
#define CIN     256
#define COUT    256
#define KTOT    2304      // CIN * 9
#define MTOT    32768     // N * H * W

// Sample-kernel tile geometry
#define TH 13
#define TW 76
#define CG 4

// 302 MB scratch: sampled im2col matrix, layout [M=32768][K=2304] (k contiguous)
__device__ float g_samp[(size_t)MTOT * KTOT];
// tf32-rounded weights, [COUT][KTOT]
__device__ float g_wr[(size_t)COUT * KTOT];

// ============================ helpers ============================
__device__ __forceinline__ uint32_t smem_u32(const void* p) {
    uint32_t a;
    asm("{ .reg .u64 t; cvta.to.shared.u64 t, %1; cvt.u32.u64 %0, t; }"
        : "=r"(a) : "l"(p));
    return a;
}
__device__ __forceinline__ uint32_t tf32_rna(float v) {
    uint32_t r;
    asm("cvt.rna.tf32.f32 %0, %1;" : "=r"(r) : "f"(v));
    return r;
}
__device__ __forceinline__ void cp_async16(uint32_t dst, const void* src) {
    asm volatile("cp.async.cg.shared.global [%0], [%1], 16;"
                 :: "r"(dst), "l"(src) : "memory");
}
#define CP_COMMIT()  asm volatile("cp.async.commit_group;" ::: "memory")
#define CP_WAIT(n)   asm volatile("cp.async.wait_group %0;" :: "n"(n) : "memory")

__device__ __forceinline__ void ldsm_x4(uint32_t& r0, uint32_t& r1,
                                        uint32_t& r2, uint32_t& r3, uint32_t addr) {
    asm volatile("ldmatrix.sync.aligned.m8n8.x4.shared.b16 {%0,%1,%2,%3}, [%4];"
                 : "=r"(r0), "=r"(r1), "=r"(r2), "=r"(r3) : "r"(addr));
}
__device__ __forceinline__ void ldsm_x2(uint32_t& r0, uint32_t& r1, uint32_t addr) {
    asm volatile("ldmatrix.sync.aligned.m8n8.x2.shared.b16 {%0,%1}, [%2];"
                 : "=r"(r0), "=r"(r1) : "r"(addr));
}
__device__ __forceinline__ void mma_tf32(float* c, const uint32_t* a, const uint32_t* b) {
    asm volatile(
        "mma.sync.aligned.m16n8k8.row.col.f32.tf32.tf32.f32 "
        "{%0,%1,%2,%3}, {%4,%5,%6,%7}, {%8,%9}, {%0,%1,%2,%3};"
        : "+f"(c[0]), "+f"(c[1]), "+f"(c[2]), "+f"(c[3])
        : "r"(a[0]), "r"(a[1]), "r"(a[2]), "r"(a[3]), "r"(b[0]), "r"(b[1]));
}

// ---------------- Kernel 0: round weights to tf32 once ----------------
__global__ __launch_bounds__(256) void round_w(const float* __restrict__ w) {
    int i = blockIdx.x * 256 + threadIdx.x;
    if (i < COUT * KTOT)
        g_wr[i] = __uint_as_float(tf32_rna(w[i]));
}

// ---------------- Kernel 1: OBB anchor sampling -> im2col scratch [M][K] ----------------
// Offsets cancel: sample position == rotated box anchor. Zero-padded bilinear.
__global__ __launch_bounds__(256) void sample_kernel(
    const float* __restrict__ x,
    const float* __restrict__ obb,
    const unsigned* __restrict__ stride_ptr)
{
    __shared__ int    s_idx[576];
    __shared__ float4 s_w[576];
    __shared__ float  s_tile[CG * TH * TW];
    __shared__ float  s_out[64][37];    // [pixel][k_local], pitch 37 (conflict-free)

    const int tid = threadIdx.x;
    const int m0  = blockIdx.x * 64;
    const int n   = m0 >> 14;
    const int hw0 = m0 & 16383;
    const int h   = hw0 >> 7;
    const int w0  = hw0 & 127;

    unsigned su = *stride_ptr;
    float s = (su < 0x00800000u) ? (float)su : __uint_as_float(su);

    for (int e = tid; e < 576; e += 256) {
        int tap = e >> 6;
        int p   = e & 63;
        int w   = w0 + p;
        const float* ob = obb + (size_t)n * 5 * 16384 + h * 128 + w;
        float xc = ob[0]         / s;
        float yc = ob[16384]     / s;
        float bw = ob[2 * 16384] / s;
        float bh = ob[3 * 16384] / s;
        float th = ob[4 * 16384];
        float sn, cs;
        __sincosf(th, &sn, &cs);
        float kx = (float)(tap % 3 - 1);
        float ky = (float)(tap / 3 - 1);
        float px = bw * (1.0f / 3.0f) * kx;
        float py = bh * (1.0f / 3.0f) * ky;
        float xa = cs * px - sn * py + xc;
        float ya = sn * px + cs * py + yc;
        float fx = floorf(xa), fy = floorf(ya);
        float lx = xa - fx,    ly = ya - fy;
        int r   = (int)fy - (h - 6);
        int col = (int)fx - (w0 - 6);
        r   = min(max(r, 0), TH - 2);
        col = min(max(col, 0), TW - 2);
        s_idx[e] = r * TW + col;
        s_w[e] = make_float4((1.f - ly) * (1.f - lx),
                             (1.f - ly) * lx,
                             ly * (1.f - lx),
                             ly * lx);
    }

    const float* xn = x + (size_t)n * CIN * 16384;

    for (int c0 = 0; c0 < CIN; c0 += CG) {
        __syncthreads();   // protect s_tile & s_out reuse
        for (int i = tid; i < CG * TH * TW; i += 256) {
            int cc  = i / (TH * TW);
            int rem = i - cc * (TH * TW);
            int rr  = rem / TW;
            int col = rem - rr * TW;
            int gy = h - 6 + rr;
            int gx = w0 - 6 + col;
            float v = 0.f;
            if ((unsigned)gy < 128u && (unsigned)gx < 128u)
                v = __ldg(xn + (size_t)(c0 + cc) * 16384 + gy * 128 + gx);
            s_tile[i] = v;
        }
        __syncthreads();
        #pragma unroll
        for (int j = 0; j < 9; j++) {
            int t2 = tid + (j << 8);
            int cl = t2 / 576;
            int e  = t2 - cl * 576;
            const float* tb = s_tile + cl * (TH * TW);
            int ii = s_idx[e];
            float4 wv = s_w[e];
            float v = wv.x * tb[ii] + wv.y * tb[ii + 1]
                    + wv.z * tb[ii + TW] + wv.w * tb[ii + TW + 1];
            s_out[e & 63][cl * 9 + (e >> 6)] = __uint_as_float(tf32_rna(v));
        }
        __syncthreads();
        // Writeback: 64 rows x 36 floats, coalesced 144B rows (16B aligned)
        for (int i = tid; i < 576; i += 256) {
            int row = i / 9;
            int q   = i - row * 9;
            float4 v4 = make_float4(s_out[row][q * 4],     s_out[row][q * 4 + 1],
                                    s_out[row][q * 4 + 2], s_out[row][q * 4 + 3]);
            *(float4*)&g_samp[(size_t)(m0 + row) * KTOT + c0 * 9 + q * 4] = v4;
        }
    }
}

// ---------------- Kernel 2: mma.sync TF32 GEMM, ldmatrix fragments ----------------
// CTA: 128 couts (M) x 256 pixels (N). Warps 2(M) x 4(N), warp tile 64x64.
// A = weights SMEM [cout][k] pitch 36;  B = pixels SMEM [pix][k] pitch 36.
// K chunks of 32, cp.async double buffer.

#define PITCH  36
#define A_BUF  (128 * PITCH)      // floats per buffer
#define B_BUF  (256 * PITCH)
#define KCHUNK 32
#define NCHUNKS (KTOT / KCHUNK)   // 72
#define SMEM_DYN ((2 * A_BUF + 2 * B_BUF) * 4)   // 110592 B

__global__ __launch_bounds__(256, 1) void gemm_mma(float* __restrict__ out)
{
    extern __shared__ __align__(16) float sm[];
    float* As = sm;                 // [2][128][PITCH]
    float* Bs = sm + 2 * A_BUF;     // [2][256][PITCH]

    const int tid  = threadIdx.x;
    const int lane = tid & 31;
    const int wid  = tid >> 5;
    const int lq   = lane >> 2;
    const int lt   = lane & 3;
    const int warp_m = (wid & 1) << 6;    // 0 / 64 (couts)
    const int warp_n = (wid >> 1) << 6;   // 0,64,128,192 (pixels)
    const int m0c = blockIdx.x << 7;      // cout base (x fastest -> L2 pair share)
    const int n0p = blockIdx.y << 8;      // pixel base

    const uint32_t as_u = smem_u32(As);
    const uint32_t bs_u = smem_u32(Bs);

    // ldmatrix lane address components (byte offsets within buffer)
    const uint32_t a_row = (uint32_t)(warp_m + (lane & 15));
    const uint32_t a_ko  = ((lane >> 4) & 1) << 2;
    const uint32_t b_row = (uint32_t)(warp_n + (lane & 7));
    const uint32_t b_ko  = ((lane >> 3) & 1) << 2;

    float acc[4][8][4];
    #pragma unroll
    for (int i = 0; i < 4; i++)
        #pragma unroll
        for (int j = 0; j < 8; j++)
            #pragma unroll
            for (int r = 0; r < 4; r++)
                acc[i][j][r] = 0.f;

    auto stage = [&](int c, int buf) {
        const float* Aw = g_wr + (size_t)m0c * KTOT + c * KCHUNK;
        uint32_t ad = as_u + (uint32_t)buf * (A_BUF * 4);
        #pragma unroll
        for (int i = 0; i < 4; i++) {
            int id = tid + (i << 8);       // 0..1023
            int r  = id >> 3;
            int q  = id & 7;
            cp_async16(ad + (uint32_t)(r * PITCH + q * 4) * 4,
                       Aw + (size_t)r * KTOT + q * 4);
        }
        const float* Bg = g_samp + (size_t)n0p * KTOT + c * KCHUNK;
        uint32_t bd = bs_u + (uint32_t)buf * (B_BUF * 4);
        #pragma unroll
        for (int i = 0; i < 8; i++) {
            int id = tid + (i << 8);       // 0..2047
            int r  = id >> 3;
            int q  = id & 7;
            cp_async16(bd + (uint32_t)(r * PITCH + q * 4) * 4,
                       Bg + (size_t)r * KTOT + q * 4);
        }
        CP_COMMIT();
    };

    stage(0, 0);

    for (int c = 0; c < NCHUNKS; c++) {
        int buf = c & 1;
        if (c + 1 < NCHUNKS) {
            stage(c + 1, buf ^ 1);
            CP_WAIT(1);
        } else {
            CP_WAIT(0);
        }
        __syncthreads();

        const uint32_t ab = as_u + (uint32_t)buf * (A_BUF * 4);
        const uint32_t bb = bs_u + (uint32_t)buf * (B_BUF * 4);

        #pragma unroll
        for (int s = 0; s < 4; s++) {
            const uint32_t ks = (uint32_t)(s << 3);
            uint32_t b[8][2];
            #pragma unroll
            for (int bn = 0; bn < 8; bn++) {
                uint32_t addr = bb + (uint32_t)((b_row + (bn << 3)) * PITCH + ks + b_ko) * 4;
                ldsm_x2(b[bn][0], b[bn][1], addr);
            }
            #pragma unroll
            for (int am = 0; am < 4; am++) {
                uint32_t a[4];
                uint32_t addr = ab + (uint32_t)((a_row + (am << 4)) * PITCH + ks + a_ko) * 4;
                ldsm_x4(a[0], a[1], a[2], a[3], addr);
                #pragma unroll
                for (int bn = 0; bn < 8; bn++)
                    mma_tf32(acc[am][bn], a, b[bn]);
            }
        }
        __syncthreads();
    }

    // Epilogue: out[img][cout][hw]; C frag: rows=cout (lq,+8), cols=pixels (2lt,2lt+1)
    #pragma unroll
    for (int am = 0; am < 4; am++) {
        #pragma unroll
        for (int bn = 0; bn < 8; bn++) {
            int cout = m0c + warp_m + (am << 4) + lq;
            int pix  = n0p + warp_n + (bn << 3) + (lt << 1);
            int img  = pix >> 14;
            int hw   = pix & 16383;
            float* p0 = out + ((size_t)img << 22) + ((size_t)cout << 14) + hw;
            *(float2*)p0 = make_float2(acc[am][bn][0], acc[am][bn][1]);
            *(float2*)(p0 + ((size_t)8 << 14)) =
                make_float2(acc[am][bn][2], acc[am][bn][3]);
        }
    }
}

extern "C" void kernel_launch(void* const* d_in, const int* in_sizes, int n_in,
                              void* d_out, int out_size) {
    const float*    x   = (const float*)d_in[0];
    const float*    obb = (const float*)d_in[1];
    const float*    wt  = (const float*)d_in[2];
    const unsigned* st  = (const unsigned*)d_in[3];
    float* out = (float*)d_out;

    cudaFuncSetAttribute(gemm_mma, cudaFuncAttributeMaxDynamicSharedMemorySize, SMEM_DYN);

    round_w<<<(COUT * KTOT + 255) / 256, 256>>>(wt);
    sample_kernel<<<MTOT / 64, 256>>>(x, obb, st);
    dim3 g(COUT / 128, MTOT / 256);
    gemm_mma<<<g, 256, SMEM_DYN>>>(out);
}